// round 14
// baseline (speedup 1.0000x reference)
#include <cuda_runtime.h>
#include <cuda_fp16.h>
#include <cstdint>

// Problem constants
#define NB    32
#define CIN   128
#define HH    112
#define WW    112
#define COUT  256
#define TH    8
#define TW    16

// SMEM: input patch only (128 ch, 10x18 cells, 272B cells -> conflict-free ldsm)
#define P_CELL   272
#define P_COLS   18
#define P_ROWS   10
#define P_BYTES  (P_ROWS * P_COLS * P_CELL)   // 48960
#define S_TOTAL  P_BYTES

// Fragment-major fp16 weights (validated R13):
// uint4 index = ((((ocg*9+tap)*8+k16)*2+wm)*4+mt)*32 + lane
__device__ uint4 g_wF[2 * 9 * 8 * 2 * 4 * 32];   // 576 KB

// ---------------------------------------------------------------------------
// Helpers
// ---------------------------------------------------------------------------
__device__ __forceinline__ uint32_t smem_u32(const void* p) {
    uint32_t a;
    asm("{ .reg .u64 t; cvta.to.shared.u64 t, %1; cvt.u32.u64 %0, t; }"
        : "=r"(a) : "l"(p));
    return a;
}
__device__ __forceinline__ void ldsm4(uint32_t* r, uint32_t addr) {
    asm volatile("ldmatrix.sync.aligned.m8n8.x4.shared.b16 {%0,%1,%2,%3}, [%4];"
                 : "=r"(r[0]), "=r"(r[1]), "=r"(r[2]), "=r"(r[3]) : "r"(addr));
}
__device__ __forceinline__ void mma16816(float* d, uint4 a, const uint32_t* b) {
    asm volatile(
        "mma.sync.aligned.m16n8k16.row.col.f32.f16.f16.f32 "
        "{%0,%1,%2,%3}, {%4,%5,%6,%7}, {%8,%9}, {%0,%1,%2,%3};"
        : "+f"(d[0]), "+f"(d[1]), "+f"(d[2]), "+f"(d[3])
        : "r"(a.x), "r"(a.y), "r"(a.z), "r"(a.w), "r"(b[0]), "r"(b[1]));
}
__device__ __forceinline__ uint32_t pkh(float a, float b) {
    __half ha = __float2half_rn(a), hb = __float2half_rn(b);
    return (uint32_t)__half_as_ushort(ha) |
           ((uint32_t)__half_as_ushort(hb) << 16);
}

// ---------------------------------------------------------------------------
// Kernel 1: write fragment-major fp16 weights (validated R13).
// ---------------------------------------------------------------------------
__global__ void wprep_kernel(const float* __restrict__ w) {
    int j = blockIdx.x * blockDim.x + threadIdx.x;
    if (j >= 36864) return;
    const int lane = j & 31;
    const int mt   = (j >> 5) & 3;
    const int wm   = (j >> 7) & 1;
    const int k16  = (j >> 8) & 7;
    const int tj   = j >> 11;            // ocg*9 + tap
    const int ocg  = tj / 9;
    const int tap  = tj - ocg * 9;

    const int oc0 = ocg * 128 + wm * 64 + mt * 16 + (lane >> 2);
    const int c0  = k16 * 16 + (lane & 3) * 2;

    auto W = [&](int oc, int c) -> float {
        return w[((size_t)oc * CIN + c) * 9 + tap];
    };
    uint4 v;
    v.x = pkh(W(oc0,     c0),     W(oc0,     c0 + 1));
    v.y = pkh(W(oc0 + 8, c0),     W(oc0 + 8, c0 + 1));
    v.z = pkh(W(oc0,     c0 + 8), W(oc0,     c0 + 9));
    v.w = pkh(W(oc0 + 8, c0 + 8), W(oc0 + 8, c0 + 9));
    g_wF[j] = v;
}

// ---------------------------------------------------------------------------
// Kernel 2: implicit-GEMM conv, single-stream fp16 MMA.
// 1 CTA/SM (255-reg budget) -> explicit software pipeline:
//   A fragments: LDG register ring, depth 3 (covers L2 latency)
//   B fragments: LDSM double buffer, depth 1
//   zero mainloop barriers (single sync after the one-time patch build)
// grid = (98, 32, 2), block = 256
// ---------------------------------------------------------------------------
extern __shared__ unsigned char smem[];

__global__ __launch_bounds__(256, 1)
void conv_mma_kernel(const float* __restrict__ in,
                     const float* __restrict__ bias,
                     float* __restrict__ out) {
    const int tid = threadIdx.x;
    const int wid = tid >> 5;
    const int lid = tid & 31;
    const int wm  = wid & 1;           // M half (64 oc)
    const int wn  = wid >> 1;          // N quarter (32 px)

    const int n   = blockIdx.y;
    const int ocg = blockIdx.z;
    const int h0  = (blockIdx.x / 7) * TH;
    const int w0  = (blockIdx.x % 7) * TW;

    const uint32_t sb = smem_u32(smem);

    // ---- per-lane B ldmatrix address components (validated R6-R13) ----
    const int nb_n   = (lid & 7) + ((lid >> 4) << 3);
    const uint32_t khoff = (uint32_t)(((lid >> 3) & 1) * 16);
    const int px0 = wn * 32 + nb_n;
    const int px1 = px0 + 16;
    const uint32_t bc0 =
        sb + (uint32_t)(((px0 >> 4) * P_COLS + (px0 & 15)) * P_CELL) + khoff;
    const uint32_t bc1 =
        sb + (uint32_t)(((px1 >> 4) * P_COLS + (px1 & 15)) * P_CELL) + khoff;

    // ---- A fragment base pointer (fragment-major global layout) ----
    const uint4* fb = g_wF + (size_t)ocg * 18432 + wm * 128 + lid;

    // ---- A ring preamble: u = 0,1,2 (latency hidden under patch build) ----
    uint4 af[3][4];
#pragma unroll
    for (int s = 0; s < 3; ++s)
#pragma unroll
        for (int mt = 0; mt < 4; ++mt)
            af[s][mt] = __ldg(fb + (size_t)s * 256 + mt * 32);
    const uint4* apf = fb + 3 * 256;   // next A prefetch target (u+3)

    // ---- accumulators, bias-initialized ----
    float acc[4][4][4];
    {
        const int r0 = lid >> 2;
#pragma unroll
        for (int mt = 0; mt < 4; ++mt) {
            const int oc0 = ocg * 128 + wm * 64 + mt * 16 + r0;
            const float b0 = __ldg(&bias[oc0]);
            const float b1 = __ldg(&bias[oc0 + 8]);
#pragma unroll
            for (int nt = 0; nt < 4; ++nt) {
                acc[mt][nt][0] = b0; acc[mt][nt][1] = b0;
                acc[mt][nt][2] = b1; acc[mt][nt][3] = b1;
            }
        }
    }

    const float* inb = in + (size_t)n * CIN * HH * WW;

    // ---- patch build (all 128 ch), 90 elements/thread, incremental counters ----
    {
        int cc = tid / 180;
        int rm = tid - cc * 180;
        int yy = rm / 18;
        int xx = rm - yy * 18;
        for (int k = 0; k < 90; ++k) {
            const int gy = h0 - 1 + yy;
            const int gx = w0 - 1 + xx;
            float v = 0.0f;
            if (gy >= 0 && gy < HH && gx >= 0 && gx < WW)
                v = __ldg(&inb[((size_t)cc * HH + gy) * WW + gx]);
            const uint32_t cell =
                (uint32_t)((yy * P_COLS + xx) * P_CELL + cc * 2);
            *(__half*)(smem + cell) = __float2half_rn(v);
            // advance by 256 = 1*180 + 76 (76 = 4*18 + 4)
            cc += 1; yy += 4; xx += 4;
            if (xx >= 18) { xx -= 18; yy += 1; }
            if (yy >= 10) { yy -= 10; cc += 1; }
        }
    }
    __syncthreads();   // the ONLY barrier

    // ---- B double-buffer preamble: u = 0 (tap 0, k16 0) ----
    uint32_t bf[2][8];
    ldsm4(bf[0],     bc0);
    ldsm4(bf[0] + 4, bc1);

    // tap-address state for u+1 computation: current u's (toff, bkb, kw)
    uint32_t toff = 0, bkb = 0;
    int kwc = 0;

    // ---- barrier-free pipelined mainloop: 72 units, 6-unrolled ----
    for (int base = 0; base < 72; base += 6) {
#pragma unroll
        for (int i = 0; i < 6; ++i) {
            const int u = base + i;

            // next-unit B address (u+1)
            uint32_t nbkb = bkb + 32, ntoff = toff;
            int nkw = kwc;
            if (nbkb == 256) {
                nbkb = 0; ntoff += P_CELL; nkw++;
                if (nkw == 3) { nkw = 0; ntoff += 15 * P_CELL; }
            }

            // prefetch B for u+1 (LDSM latency covered by this unit's MMAs)
            if (u < 71) {
                ldsm4(bf[(i + 1) & 1],     bc0 + ntoff + nbkb);
                ldsm4(bf[(i + 1) & 1] + 4, bc1 + ntoff + nbkb);
            }

            // MMAs on current fragments
#pragma unroll
            for (int mt = 0; mt < 4; ++mt)
#pragma unroll
                for (int nt = 0; nt < 4; ++nt)
                    mma16816(acc[mt][nt], af[i % 3][mt], bf[i & 1] + nt * 2);

            // prefetch A for u+3 into the slot just consumed (L2 latency
            // covered by the next ~3 units of MMAs)
            if (u < 69) {
#pragma unroll
                for (int mt = 0; mt < 4; ++mt)
                    af[i % 3][mt] = __ldg(apf + mt * 32);
            }
            apf += 256;

            toff = ntoff; bkb = nbkb; kwc = nkw;
        }
    }

    // ---- epilogue: direct register -> global stores ----
    {
        const int r0 = lid >> 2;
        const int cp = (lid & 3) * 2;
#pragma unroll
        for (int mt = 0; mt < 4; ++mt) {
            const int oc0 = ocg * 128 + wm * 64 + mt * 16 + r0;
            float* ob0 = out + (((size_t)n * COUT + oc0) * HH + h0) * WW + w0;
            float* ob1 = ob0 + (size_t)8 * HH * WW;
#pragma unroll
            for (int nt = 0; nt < 4; ++nt) {
                const int px = wn * 32 + nt * 8 + cp;
                const int py = px >> 4;
                const int pw = px & 15;
                const size_t o = (size_t)py * WW + pw;
                *(float2*)(ob0 + o) = make_float2(acc[mt][nt][0], acc[mt][nt][1]);
                *(float2*)(ob1 + o) = make_float2(acc[mt][nt][2], acc[mt][nt][3]);
            }
        }
    }
}

// ---------------------------------------------------------------------------
// Launch
// ---------------------------------------------------------------------------
extern "C" void kernel_launch(void* const* d_in, const int* in_sizes, int n_in,
                              void* d_out, int out_size) {
    const float* input  = (const float*)d_in[0];   // (32,128,112,112)
    const float* weight = (const float*)d_in[1];   // (256,128,3,3)
    const float* bias   = (const float*)d_in[2];   // (256,)
    float* out = (float*)d_out;                    // (32,256,112,112)

    static bool configured = false;
    if (!configured) {
        cudaFuncSetAttribute(conv_mma_kernel,
                             cudaFuncAttributeMaxDynamicSharedMemorySize,
                             S_TOTAL);
        configured = true;
    }

    wprep_kernel<<<(36864 + 255) / 256, 256>>>(weight);

    dim3 grid(14 * 7, NB, 2);   // 98 x 32 x 2
    conv_mma_kernel<<<grid, 256, S_TOTAL>>>(input, bias, out);
}

// round 15
// speedup vs baseline: 1.9497x; 1.9497x over previous
#include <cuda_runtime.h>
#include <cuda_fp16.h>
#include <cstdint>

// Problem constants
#define NB    32
#define CIN   128
#define HH    112
#define WW    112
#define COUT  256
#define TH    8
#define TW    16

// SMEM layout (dynamic)
#define A_TILE   16384              // 128 oc x 64 c fp16, SW128-swizzled
#define NBUF     3                  // A-tile ring depth
#define P_CELL   144                // bytes per (y,x) cell: 64ch*2B + 16B pad
#define P_BYTES  (180 * P_CELL)     // 10*18 cells = 25920 B
#define S_P      (NBUF * A_TILE)    // 49152
#define S_TOTAL  (S_P + P_BYTES)    // 75072 -> 2 CTAs/SM

// Pre-rounded fp16 weights: [ocg(2)][cblk(2)][tap(9)] 16KB tiles, SW128-swizzled
__device__ unsigned char g_wA[2 * 2 * 9 * A_TILE];   // 576 KB

// ---------------------------------------------------------------------------
// Helpers
// ---------------------------------------------------------------------------
__device__ __forceinline__ uint32_t swz128(uint32_t off) {
    return off ^ ((off >> 3) & 0x70);
}
__device__ __forceinline__ uint32_t smem_u32(const void* p) {
    uint32_t a;
    asm("{ .reg .u64 t; cvta.to.shared.u64 t, %1; cvt.u32.u64 %0, t; }"
        : "=r"(a) : "l"(p));
    return a;
}
__device__ __forceinline__ void ldsm4(uint32_t* r, uint32_t addr) {
    asm volatile("ldmatrix.sync.aligned.m8n8.x4.shared.b16 {%0,%1,%2,%3}, [%4];"
                 : "=r"(r[0]), "=r"(r[1]), "=r"(r[2]), "=r"(r[3]) : "r"(addr));
}
__device__ __forceinline__ void mma16816(float* d, const uint32_t* a,
                                         const uint32_t* b) {
    asm volatile(
        "mma.sync.aligned.m16n8k16.row.col.f32.f16.f16.f32 "
        "{%0,%1,%2,%3}, {%4,%5,%6,%7}, {%8,%9}, {%0,%1,%2,%3};"
        : "+f"(d[0]), "+f"(d[1]), "+f"(d[2]), "+f"(d[3])
        : "r"(a[0]), "r"(a[1]), "r"(a[2]), "r"(a[3]), "r"(b[0]), "r"(b[1]));
}
__device__ __forceinline__ void cpasync16(uint32_t dst, const void* src) {
    asm volatile("cp.async.cg.shared.global [%0], [%1], 16;"
                 :: "r"(dst), "l"(src) : "memory");
}

// ---------------------------------------------------------------------------
// Kernel 1: round weights to fp16 tiles [ocg][cblk][tap], SW128-swizzled.
// (validated R7-R9)
// ---------------------------------------------------------------------------
__global__ void wprep_kernel(const float* __restrict__ w) {
    int j = blockIdx.x * blockDim.x + threadIdx.x;   // 256 oc * 9 tap * 64 cpair
    if (j >= 256 * 9 * 64) return;
    int cpair = j & 63;
    int tap   = (j >> 6) % 9;
    int oc    = j / 576;
    int c     = cpair * 2;
    int ocg   = oc >> 7, ocl = oc & 127;
    int cblk  = c >> 6,  cl  = c & 63;

    __half h0 = __float2half_rn(w[((size_t)oc * CIN + c) * 9 + tap]);
    __half h1 = __float2half_rn(w[((size_t)oc * CIN + c + 1) * 9 + tap]);
    uint32_t hi = (uint32_t)__half_as_ushort(h0) |
                  ((uint32_t)__half_as_ushort(h1) << 16);

    size_t base = (size_t)(((ocg * 2 + cblk) * 9 + tap)) * A_TILE;
    uint32_t off = swz128((uint32_t)(ocl * 128 + cl * 2));
    *(uint32_t*)(g_wA + base + off) = hi;
}

// ---------------------------------------------------------------------------
// Kernel 2: implicit-GEMM conv, single-stream fp16 MMA (R9 structure,
// verified 749.8us) + per-warp k16 ROTATION: each warp walks the 4 k16
// blocks starting at (wid & 3), de-phase-locking the post-barrier LDSM
// bursts across the 16 resident warps so crossbar service of some warps
// overlaps MMA issue of others.
// grid = (98, 32, 2), block = 256, 2 CTAs/SM
// ---------------------------------------------------------------------------
extern __shared__ unsigned char smem[];

__global__ __launch_bounds__(256, 2)
void conv_mma_kernel(const float* __restrict__ in,
                     const float* __restrict__ bias,
                     float* __restrict__ out) {
    const int tid = threadIdx.x;
    const int wid = tid >> 5;
    const int lid = tid & 31;
    const int wm  = wid & 1;           // M half (64 oc)
    const int wn  = wid >> 1;          // N quarter (32 px)

    const int n   = blockIdx.y;
    const int ocg = blockIdx.z;
    const int h0  = (blockIdx.x / 7) * TH;
    const int w0  = (blockIdx.x % 7) * TW;

    const uint32_t sb = smem_u32(smem);

    // ---- accumulators, bias-initialized ----
    float acc[4][4][4];
    {
        const int r0 = lid >> 2;
#pragma unroll
        for (int mt = 0; mt < 4; ++mt) {
            const int oc0 = ocg * 128 + wm * 64 + mt * 16 + r0;
            const float b0 = __ldg(&bias[oc0]);
            const float b1 = __ldg(&bias[oc0 + 8]);
#pragma unroll
            for (int nt = 0; nt < 4; ++nt) {
                acc[mt][nt][0] = b0; acc[mt][nt][1] = b0;
                acc[mt][nt][2] = b1; acc[mt][nt][3] = b1;
            }
        }
    }

    // ---- per-lane ldmatrix address components (validated R6-R14) ----
    const uint32_t a_row = (uint32_t)(wm * 64 + (lid & 15));
    const uint32_t a_col = (uint32_t)((lid >> 4) << 4);
    const int nb_n   = (lid & 7) + ((lid >> 4) << 3);
    const uint32_t khoff = (uint32_t)(((lid >> 3) & 1) * 16);
    const int px0 = wn * 32 + nb_n;
    const int px1 = px0 + 16;
    const uint32_t bc0 = (uint32_t)(((px0 >> 4) * 18 + (px0 & 15)) * P_CELL) + khoff;
    const uint32_t bc1 = (uint32_t)(((px1 >> 4) * 18 + (px1 & 15)) * P_CELL) + khoff;

    const float* inb = in + (size_t)n * CIN * HH * WW;

    // one patch element: index i (< 64*180) of channel block cb -> (value, cell)
    auto ld_elem = [&](int i, int cb) -> float {
        const int c = i / 180;
        const int r = i - c * 180;
        const int y = r / 18;
        const int x = r - y * 18;
        const int gy = h0 - 1 + y;
        const int gx = w0 - 1 + x;
        float v = 0.0f;
        if (gy >= 0 && gy < HH && gx >= 0 && gx < WW)
            v = __ldg(&inb[((size_t)(cb * 64 + c) * HH + gy) * WW + gx]);
        return v;
    };
    auto cell_of = [&](int i) -> uint32_t {
        const int c = i / 180;
        const int r = i - c * 180;
        return (uint32_t)(r * P_CELL + c * 2);
    };

    // ---- A-tile prefetch (16KB per tap, 3-deep ring) ----
    auto prefetchA = [&](int j) {
        const unsigned char* src =
            g_wA + (size_t)((ocg * 2 + (j / 9)) * 9 + (j % 9)) * A_TILE;
        const uint32_t dst = sb + (uint32_t)((j % NBUF) * A_TILE);
#pragma unroll
        for (int q = 0; q < 4; ++q)
            cpasync16(dst + tid * 16 + q * 4096, src + tid * 16 + q * 4096);
        asm volatile("cp.async.commit_group;" ::: "memory");
    };

    prefetchA(0);
    prefetchA(1);

    for (int cblk = 0; cblk < 2; ++cblk) {
        __syncthreads();   // prior cblk's MMAs done reading patch

        // ---- build fp16 patch: p[y][x][c], 144B cells ----
        for (int i = tid; i < 64 * 180; i += 256) {
            const int c = i / 180;
            const int r = i - c * 180;
            const int y = r / 18;
            const int x = r - y * 18;
            const int gy = h0 - 1 + y;
            const int gx = w0 - 1 + x;
            float v = 0.0f;
            if (gy >= 0 && gy < HH && gx >= 0 && gx < WW)
                v = inb[((size_t)(cblk * 64 + c) * HH + gy) * WW + gx];
            const uint32_t cell = (uint32_t)((y * 18 + x) * P_CELL + c * 2);
            *(__half*)(smem + S_P + cell) = __float2half_rn(v);
        }

        for (int tap = 0; tap < 9; ++tap) {
            const int j = cblk * 9 + tap;

            // wait for A[j]; newest committed group is j+1 (except at the end)
            if (j < 17)
                asm volatile("cp.async.wait_group 1;" ::: "memory");
            else
                asm volatile("cp.async.wait_group 0;" ::: "memory");
            __syncthreads();   // A[j] visible to all; buffer (j+2)%3 released;
                               // also orders patch build for tap 0

            if (j + 2 <= 17) prefetchA(j + 2);

            const uint32_t abuf = sb + (uint32_t)((j % NBUF) * A_TILE);
            const int kh = tap / 3, kw = tap - kh * 3;
            const uint32_t toff = (uint32_t)((kh * 18 + kw) * P_CELL);
            const uint32_t b_base = sb + S_P + toff;

#pragma unroll
            for (int k16 = 0; k16 < 4; ++k16) {
                // per-warp rotation: decorrelate post-barrier LDSM phases
                const uint32_t kb = (uint32_t)((((k16 + wid) & 3)) * 32);

                // A fragments (weights)
                uint32_t af[4][4];
#pragma unroll
                for (int mt = 0; mt < 4; ++mt)
                    ldsm4(af[mt], abuf +
                          swz128((a_row + mt * 16) * 128 + kb + a_col));

                // B fragments (inputs)
                uint32_t bf[8];
                ldsm4(bf,     b_base + bc0 + kb);
                ldsm4(bf + 4, b_base + bc1 + kb);

#pragma unroll
                for (int mt = 0; mt < 4; ++mt)
#pragma unroll
                    for (int nt = 0; nt < 4; ++nt)
                        mma16816(acc[mt][nt], af[mt], bf + nt * 2);
            }
        }
    }

    // ---- epilogue: direct register -> global stores ----
    {
        const int r0 = lid >> 2;
        const int cp = (lid & 3) * 2;
#pragma unroll
        for (int mt = 0; mt < 4; ++mt) {
            const int oc0 = ocg * 128 + wm * 64 + mt * 16 + r0;
            float* ob0 = out + (((size_t)n * COUT + oc0) * HH + h0) * WW + w0;
            float* ob1 = ob0 + (size_t)8 * HH * WW;
#pragma unroll
            for (int nt = 0; nt < 4; ++nt) {
                const int px = wn * 32 + nt * 8 + cp;
                const int py = px >> 4;
                const int pw = px & 15;
                const size_t o = (size_t)py * WW + pw;
                *(float2*)(ob0 + o) = make_float2(acc[mt][nt][0], acc[mt][nt][1]);
                *(float2*)(ob1 + o) = make_float2(acc[mt][nt][2], acc[mt][nt][3]);
            }
        }
    }
}

// ---------------------------------------------------------------------------
// Launch
// ---------------------------------------------------------------------------
extern "C" void kernel_launch(void* const* d_in, const int* in_sizes, int n_in,
                              void* d_out, int out_size) {
    const float* input  = (const float*)d_in[0];   // (32,128,112,112)
    const float* weight = (const float*)d_in[1];   // (256,128,3,3)
    const float* bias   = (const float*)d_in[2];   // (256,)
    float* out = (float*)d_out;                    // (32,256,112,112)

    static bool configured = false;
    if (!configured) {
        cudaFuncSetAttribute(conv_mma_kernel,
                             cudaFuncAttributeMaxDynamicSharedMemorySize,
                             S_TOTAL);
        configured = true;
    }

    wprep_kernel<<<(256 * 9 * 64 + 255) / 256, 256>>>(weight);

    dim3 grid(14 * 7, NB, 2);
    conv_mma_kernel<<<grid, 256, S_TOTAL>>>(input, bias, out);
}